// round 9
// baseline (speedup 1.0000x reference)
#include <cuda_runtime.h>
#include <cuda_bf16.h>
#include <math.h>

// ---------------------------------------------------------------------------
// HybridConv: out[n] = MLP(RBF(sigmoid(dot(data[n], conv_w) + conv_b)))
// out is a smooth scalar function f of t = 2*sigmoid(logit)-1 = tanh(logit/2).
// SINGLE kernel. Warp-0 prologue (per block, concurrent across blocks):
// evaluate f at 32 Chebyshev nodes (precise float), DCT via cospif -> 16
// Chebyshev coefficients in smem. Main loop: 4x LDG.128 -> dot ->
// tanh.approx(l/2) -> degree-15 Clenshaw with fma.rn.f32x2 (2 patches/instr)
// -> STG.128. No table, no launch gap, no LDS in the hot loop.
// ---------------------------------------------------------------------------

#define NCOEF 16   // Chebyshev degree 15
#define BASIS 8
#define HIDDEN 16

#define FMA2(d, a, b, c) \
    asm("fma.rn.f32x2 %0, %1, %2, %3;" \
        : "=l"(d) : "l"(a), "l"(b), "l"(c))
#define PACK2(d, lo, hi) \
    asm("mov.b64 %0, {%1, %2};" : "=l"(d) : "f"(lo), "f"(hi))
#define UNPACK2(lo, hi, s) \
    asm("mov.b64 {%0, %1}, %2;" : "=f"(lo), "=f"(hi) : "l"(s))

__device__ __forceinline__ float fast_tanh(float x) {
    float y;
    asm("tanh.approx.f32 %0, %1;" : "=f"(y) : "f"(x));
    return y;
}

// ---- scalar Clenshaw (tail path only) -------------------------------------
__device__ __forceinline__ float clenshaw_scalar(float t, const float* c) {
    float b1 = c[NCOEF - 1], b2 = 0.0f, tt = t + t;
#pragma unroll
    for (int k = NCOEF - 2; k >= 1; k--) {
        float nb = fmaf(tt, b1, c[k] - b2);
        b2 = b1; b1 = nb;
    }
    return fmaf(t, b1, c[0] - b2);           // c[0] pre-halved
}

// ---- single fused kernel --------------------------------------------------
__global__ void __launch_bounds__(256, 6)
hybridconv_kernel(const float4* __restrict__ data,
                  const float* __restrict__ conv_w,
                  const float* __restrict__ conv_b,
                  const float* __restrict__ basis,
                  const float* __restrict__ w1v,
                  const float* __restrict__ b1v,
                  const float* __restrict__ w2v,
                  const float* __restrict__ b2v,
                  float4* __restrict__ out, int n4, int n) {
    __shared__ float s_coef[NCOEF];

    // ---- prologue: warp 0 computes Chebyshev coefficients -----------------
    if (threadIdx.x < 32) {
        const int lane = threadIdx.x;
        // node: t_j = cos(pi*(2j+1)/64), act a = (1+t)/2
        float t_node = cospif((float)(2 * lane + 1) * (1.0f / 64.0f));
        float a = 0.5f + 0.5f * t_node;

        float feats[BASIS];
#pragma unroll
        for (int j = 0; j < BASIS; j++) {
            float s = 0.0f;
#pragma unroll
            for (int k = 0; k < 4; k++) {
                float d = a - basis[j * 4 + k];
                s = fmaf(d, d, s);
            }
            feats[j] = expf(-s);             // GAMMA = 1, precise
        }
        float fv = b2v[0];
#pragma unroll
        for (int i = 0; i < HIDDEN; i++) {
            float p = b1v[i];
#pragma unroll
            for (int j = 0; j < BASIS; j++)
                p = fmaf(feats[j], w1v[j * HIDDEN + i], p);
            fv = fmaf(tanhf(p), w2v[i], fv);
        }

        // DCT: c_k = (1/16) sum_j f_j cos(pi*k*(2j+1)/64); lane = k.
        // Full-warp shuffles — every lane participates.
        float ck = 0.0f;
#pragma unroll 4
        for (int j = 0; j < 32; j++) {
            float fj = __shfl_sync(0xFFFFFFFFu, fv, j);
            float w  = cospif((float)(lane * (2 * j + 1)) * (1.0f / 64.0f));
            ck = fmaf(fj, w, ck);
        }
        ck *= (1.0f / 16.0f);
        if (lane == 0) ck *= 0.5f;           // store c0/2 directly
        if (lane < NCOEF) s_coef[lane] = ck;
    }
    __syncthreads();

    float c[NCOEF];
#pragma unroll
    for (int k = 0; k < NCOEF; k++) c[k] = s_coef[k];

    const float w0 = conv_w[0], w1 = conv_w[1];
    const float w2 = conv_w[2], w3 = conv_w[3];
    const float bb = conv_b[0];

    unsigned long long negone;
    PACK2(negone, -1.0f, -1.0f);

    const int stride = gridDim.x * blockDim.x;
    int gid = blockIdx.x * blockDim.x + threadIdx.x;

    for (int i = gid; i < n4; i += stride) {
        const float4* p = data + 4 * i;
        float4 v0 = __ldcs(p + 0);
        float l0 = fmaf(v0.x, w0, fmaf(v0.y, w1, fmaf(v0.z, w2, fmaf(v0.w, w3, bb))));
        float4 v1 = __ldcs(p + 1);
        float l1 = fmaf(v1.x, w0, fmaf(v1.y, w1, fmaf(v1.z, w2, fmaf(v1.w, w3, bb))));
        float4 v2 = __ldcs(p + 2);
        float l2 = fmaf(v2.x, w0, fmaf(v2.y, w1, fmaf(v2.z, w2, fmaf(v2.w, w3, bb))));
        float4 v3 = __ldcs(p + 3);
        float l3 = fmaf(v3.x, w0, fmaf(v3.y, w1, fmaf(v3.z, w2, fmaf(v3.w, w3, bb))));

        // t = 2*sigmoid(l)-1 = tanh(l/2): one MUFU each
        float t0 = fast_tanh(0.5f * l0);
        float t1 = fast_tanh(0.5f * l1);
        float t2 = fast_tanh(0.5f * l2);
        float t3 = fast_tanh(0.5f * l3);

        unsigned long long tA, tB, ttA, ttB;
        PACK2(tA, t0, t1);
        PACK2(tB, t2, t3);
        PACK2(ttA, t0 + t0, t1 + t1);
        PACK2(ttB, t2 + t2, t3 + t3);

        // Clenshaw, two f32x2 chains (patches {0,1} and {2,3})
        unsigned long long b1A, b1B, b2A = 0ull, b2B = 0ull;
        PACK2(b1A, c[NCOEF - 1], c[NCOEF - 1]);
        b1B = b1A;
#pragma unroll
        for (int k = NCOEF - 2; k >= 1; k--) {
            unsigned long long ck2, sA, sB, nA, nB;
            PACK2(ck2, c[k], c[k]);
            FMA2(sA, b2A, negone, ck2);      // c_k - b2
            FMA2(sB, b2B, negone, ck2);
            FMA2(nA, ttA, b1A, sA);          // 2t*b1 + (c_k - b2)
            FMA2(nB, ttB, b1B, sB);
            b2A = b1A; b1A = nA;
            b2B = b1B; b1B = nB;
        }
        unsigned long long c02, sA, sB, rA, rB;
        PACK2(c02, c[0], c[0]);              // c0/2 pre-halved
        FMA2(sA, b2A, negone, c02);
        FMA2(sB, b2B, negone, c02);
        FMA2(rA, tA, b1A, sA);
        FMA2(rB, tB, b1B, sB);

        float4 r;
        UNPACK2(r.x, r.y, rA);
        UNPACK2(r.z, r.w, rB);
        __stcs(&out[i], r);
    }

    // defensive tail (empty when n % 4 == 0)
    const float* sdata = (const float*)data;
    float* sout = (float*)out;
    for (int k = 4 * n4 + gid; k < n; k += stride) {
        float4 v = ((const float4*)sdata)[k];
        float l = fmaf(v.x, w0, fmaf(v.y, w1, fmaf(v.z, w2, fmaf(v.w, w3, bb))));
        sout[k] = clenshaw_scalar(fast_tanh(0.5f * l), c);
    }
}

extern "C" void kernel_launch(void* const* d_in, const int* in_sizes, int n_in,
                              void* d_out, int out_size) {
    const float* data   = (const float*)d_in[0];   // [N, 2, 2]
    const float* conv_w = (const float*)d_in[1];   // [2, 2]
    const float* conv_b = (const float*)d_in[2];   // [1]
    const float* basis  = (const float*)d_in[3];   // [8, 4]
    const float* w1     = (const float*)d_in[4];   // [8, 16]
    const float* b1     = (const float*)d_in[5];   // [16]
    const float* w2     = (const float*)d_in[6];   // [16, 1]
    const float* b2     = (const float*)d_in[7];   // [1]

    const int n  = in_sizes[0] / 4;  // patches
    const int n4 = n / 4;

    // single launch: 1216 blocks, 6 CTAs/SM target
    hybridconv_kernel<<<1216, 256>>>(
        (const float4*)data, conv_w, conv_b, basis, w1, b1, w2, b2,
        (float4*)d_out, n4, n);
}

// round 10
// speedup vs baseline: 1.0009x; 1.0009x over previous
#include <cuda_runtime.h>
#include <cuda_bf16.h>
#include <math.h>

// ---------------------------------------------------------------------------
// HybridConv: out[n] = MLP(RBF(sigmoid(dot(data[n], conv_w) + conv_b)))
// out = f(t), t = 2*sigmoid(logit)-1 = tanh(logit/2), f analytic on [-1,1].
// Build kernel (1 warp): f at 32 Chebyshev nodes -> DCT -> Chebyshev coeffs
// -> EXACT conversion to MONOMIAL coefficients (integer T_k matrix, built by
// recurrence). Main kernel: 4x LDG.128 -> dot -> tanh.approx(l/2) ->
// degree-11 HORNER with fma.rn.f32x2 (1 FMA2/level/pair, coeff pairs packed
// once outside the loop) -> STG.128. ~60 instrs per 4 patches.
// ---------------------------------------------------------------------------

#define NCOEF 12   // monomial degree 11
#define BASIS 8
#define HIDDEN 16

__device__ float g_coef[NCOEF];   // monomial coefficients a_0..a_11

#define FMA2(d, a, b, c) \
    asm("fma.rn.f32x2 %0, %1, %2, %3;" \
        : "=l"(d) : "l"(a), "l"(b), "l"(c))
#define PACK2(d, lo, hi) \
    asm("mov.b64 %0, {%1, %2};" : "=l"(d) : "f"(lo), "f"(hi))
#define UNPACK2(lo, hi, s) \
    asm("mov.b64 {%0, %1}, %2;" : "=f"(lo), "=f"(hi) : "l"(s))

__device__ __forceinline__ float fast_tanh(float x) {
    float y;
    asm("tanh.approx.f32 %0, %1;" : "=f"(y) : "f"(x));
    return y;
}

// ---- build: one warp. nodes -> DCT -> Chebyshev -> monomial ---------------
__global__ void build_coef_kernel(const float* __restrict__ basis,
                                  const float* __restrict__ w1,
                                  const float* __restrict__ b1,
                                  const float* __restrict__ w2,
                                  const float* __restrict__ b2) {
    __shared__ float s_e[32];
    __shared__ float s_T[NCOEF][NCOEF];   // T_k(x) power coefficients (exact ints)
    const int lane = threadIdx.x;          // 0..31

    // node: t_j = cos(pi*(2j+1)/64), act a = (1+t)/2
    float t_node = cospif((float)(2 * lane + 1) * (1.0f / 64.0f));
    float a = 0.5f + 0.5f * t_node;

    // f(a): RBF feats -> MLP (precise float)
    float feats[BASIS];
#pragma unroll
    for (int j = 0; j < BASIS; j++) {
        float s = 0.0f;
#pragma unroll
        for (int k = 0; k < 4; k++) {
            float d = a - basis[j * 4 + k];
            s = fmaf(d, d, s);
        }
        feats[j] = expf(-s);               // GAMMA = 1
    }
    float fv = b2[0];
#pragma unroll
    for (int i = 0; i < HIDDEN; i++) {
        float p = b1[i];
#pragma unroll
        for (int j = 0; j < BASIS; j++)
            p = fmaf(feats[j], w1[j * HIDDEN + i], p);
        fv = fmaf(tanhf(p), w2[i], fv);
    }

    // DCT: c_k = (1/16) sum_j f_j cos(pi*k*(2j+1)/64); lane = k. Full warp.
    float ck = 0.0f;
#pragma unroll 4
    for (int j = 0; j < 32; j++) {
        float fj = __shfl_sync(0xFFFFFFFFu, fv, j);
        float w  = cospif((float)(lane * (2 * j + 1)) * (1.0f / 64.0f));
        ck = fmaf(fj, w, ck);
    }
    ck *= (1.0f / 16.0f);
    if (lane == 0) ck *= 0.5f;             // effective e_0 = c_0/2
    s_e[lane] = ck;
    __syncwarp();

    // T_k power-basis coefficients via recurrence (exact small integers)
    if (lane == 0) {
        for (int k = 0; k < NCOEF; k++)
            for (int j = 0; j < NCOEF; j++) s_T[k][j] = 0.0f;
        s_T[0][0] = 1.0f;
        s_T[1][1] = 1.0f;
        for (int k = 2; k < NCOEF; k++)
            for (int j = 0; j <= k; j++) {
                float v = (j > 0) ? 2.0f * s_T[k - 1][j - 1] : 0.0f;
                s_T[k][j] = v - s_T[k - 2][j];
            }
    }
    __syncwarp();

    // monomial a_j = sum_k e_k * T[k][j]
    if (lane < NCOEF) {
        float acc = 0.0f;
        for (int k = 0; k < NCOEF; k++)
            acc = fmaf(s_e[k], s_T[k][lane], acc);
        g_coef[lane] = acc;
    }
}

// ---- main streaming pass --------------------------------------------------
__global__ void __launch_bounds__(256)
hybridconv_main_kernel(const float4* __restrict__ data,
                       const float* __restrict__ conv_w,
                       const float* __restrict__ conv_b,
                       float4* __restrict__ out, int n4, int n) {
    // load + pack coefficient pairs ONCE (loop-invariant)
    unsigned long long c2[NCOEF];
#pragma unroll
    for (int k = 0; k < NCOEF; k++) {
        float ck = g_coef[k];
        PACK2(c2[k], ck, ck);
    }

    const float w0 = conv_w[0], w1 = conv_w[1];
    const float w2 = conv_w[2], w3 = conv_w[3];
    const float bb = conv_b[0];

    const int stride = gridDim.x * blockDim.x;
    int gid = blockIdx.x * blockDim.x + threadIdx.x;

    for (int i = gid; i < n4; i += stride) {
        const float4* p = data + 4 * i;
        float4 v0 = __ldcs(p + 0);
        float l0 = fmaf(v0.x, w0, fmaf(v0.y, w1, fmaf(v0.z, w2, fmaf(v0.w, w3, bb))));
        float4 v1 = __ldcs(p + 1);
        float l1 = fmaf(v1.x, w0, fmaf(v1.y, w1, fmaf(v1.z, w2, fmaf(v1.w, w3, bb))));
        float4 v2 = __ldcs(p + 2);
        float l2 = fmaf(v2.x, w0, fmaf(v2.y, w1, fmaf(v2.z, w2, fmaf(v2.w, w3, bb))));
        float4 v3 = __ldcs(p + 3);
        float l3 = fmaf(v3.x, w0, fmaf(v3.y, w1, fmaf(v3.z, w2, fmaf(v3.w, w3, bb))));

        // t = 2*sigmoid(l)-1 = tanh(l/2): one MUFU each
        float t0 = fast_tanh(0.5f * l0);
        float t1 = fast_tanh(0.5f * l1);
        float t2 = fast_tanh(0.5f * l2);
        float t3 = fast_tanh(0.5f * l3);

        unsigned long long tA, tB;
        PACK2(tA, t0, t1);
        PACK2(tB, t2, t3);

        // Horner, two f32x2 chains: 1 FMA2 per level per pair
        unsigned long long hA = c2[NCOEF - 1], hB = c2[NCOEF - 1];
#pragma unroll
        for (int k = NCOEF - 2; k >= 0; k--) {
            FMA2(hA, tA, hA, c2[k]);
            FMA2(hB, tB, hB, c2[k]);
        }

        float4 r;
        UNPACK2(r.x, r.y, hA);
        UNPACK2(r.z, r.w, hB);
        __stcs(&out[i], r);
    }

    // defensive tail (empty when n % 4 == 0)
    const float* sdata = (const float*)data;
    float* sout = (float*)out;
    for (int k = 4 * n4 + gid; k < n; k += stride) {
        float4 v = ((const float4*)sdata)[k];
        float l = fmaf(v.x, w0, fmaf(v.y, w1, fmaf(v.z, w2, fmaf(v.w, w3, bb))));
        float t = fast_tanh(0.5f * l);
        float h = g_coef[NCOEF - 1];
        for (int q = NCOEF - 2; q >= 0; q--)
            h = fmaf(t, h, g_coef[q]);
        sout[k] = h;
    }
}

extern "C" void kernel_launch(void* const* d_in, const int* in_sizes, int n_in,
                              void* d_out, int out_size) {
    const float* data   = (const float*)d_in[0];   // [N, 2, 2]
    const float* conv_w = (const float*)d_in[1];   // [2, 2]
    const float* conv_b = (const float*)d_in[2];   // [1]
    const float* basis  = (const float*)d_in[3];   // [8, 4]
    const float* w1     = (const float*)d_in[4];   // [8, 16]
    const float* b1     = (const float*)d_in[5];   // [16]
    const float* w2     = (const float*)d_in[6];   // [16, 1]
    const float* b2     = (const float*)d_in[7];   // [1]

    const int n  = in_sizes[0] / 4;  // patches
    const int n4 = n / 4;

    build_coef_kernel<<<1, 32>>>(basis, w1, b1, w2, b2);

    hybridconv_main_kernel<<<1216, 256>>>(
        (const float4*)data, conv_w, conv_b, (float4*)d_out, n4, n);
}